// round 13
// baseline (speedup 1.0000x reference)
#include <cuda_runtime.h>
#include <float.h>
#include <math.h>

// Problem constants
#define Bn 8
#define In 32
#define On 32
#define Dn 8
#define Hn 14
#define Wn 14
#define Kn 9
#define WK (Wn*Kn)               // 126
#define WK2 (WK/2)               // 63 float2 columns
#define NT 256
#define NGROUP 4
#define GSZ 64                   // threads per group
#define CAPS_PER_GROUP (In/NGROUP)  // 8
#define SUBSET 26                // ceil(0.8 * 32)
#define NDROP (In - SUBSET + 1)  // 7: threshold = 7th largest
#define D_STRIDE (Hn*WK)         // 1764 floats between d-planes of one capsule
#define CAP_STRIDE (Dn*D_STRIDE) // 14112 floats between capsules
#define DW (Dn*Wn)               // 112
#define LT_PITCH 33              // padded row for transposed loss/wsel
#define FULLM 0xFFFFFFFFu

__device__ __forceinline__ void group_bar(int id) {
    asm volatile("bar.sync %0, %1;" :: "r"(id), "r"(GSZ) : "memory");
}

// Stage-1 scratch (per-group) and stage-2+ scratch live in disjoint phases.
struct Stage1 {
    float nx[NGROUP][Dn][WK];    // premultiplied n_j * x[d][j] for current cap
    float nsm[NGROUP][WK];       // per-(w,k) norm over D
    float nps[NGROUP][64];       // pair sums nsm[2p]+nsm[2p+1]
};
struct Stage2 {
    float n1s[In * Wn];          // ||x1_i|| per site (i-major)
    float lossT[Wn * LT_PITCH];  // transposed: lossT[w*33 + i]
    float wselT[Wn * LT_PITCH];  // selected weights: (l<=thr)?n1:0
    float vsh[DW];               // consensus v
    float denf[Wn];              // sum of selected weights per site
};

__global__ __launch_bounds__(NT, 5)
void conv_subset_routing_kernel(const float* __restrict__ x,
                                float* __restrict__ out) {
    __shared__ __align__(16) union { Stage1 s1; Stage2 s2; } u;
    __shared__ float x1s[In * DW];         // x1[i][d][w] (persists all stages)

    const int tid = threadIdx.x;
    const int bid = blockIdx.x;
    const int h = bid % Hn;
    const int o = (bid / Hn) % On;
    const int b = bid / (Hn * On);

    const int g  = tid >> 6;      // group 0..3
    const int lt = tid & 63;      // lane within group
    const int wid  = tid >> 5;    // warp 0..7 (CTA scope)
    const int lane = tid & 31;

    const int dd = tid / Wn;      // role (d, w) for tid < 112 (stages 2+)
    const int ww = tid % Wn;

    // base float offset of (b, i=0, o, d=0, h, w=0, k=0)
    const size_t bo_base = (size_t)(b * In * On + o) * CAP_STRIDE + (size_t)h * WK;

    float* const nxg = &u.s1.nx[g][0][0];
    float* const nsg = u.s1.nsm[g];
    float* const npg = u.s1.nps[g];
    const int barid = g + 1;
    const bool colth = (lt < WK2);          // 63 column-owner threads per group

    const float* gbase = x + bo_base + (size_t)(g * CAPS_PER_GROUP) * (On * CAP_STRIDE)
                           + 2 * lt;        // this thread's column base
    const size_t cap_step = (size_t)On * CAP_STRIDE;

    // ---- stage 1: per input cap, weighted-average over kernel positions ----
    // each 64-thread group handles 8 caps; loads TWO-DEEP double-buffered in
    // registers (rvA/rvB ping-pong, prefetch distance 2) so DRAM latency is
    // covered by ~2 full cap iterations; D-norm computed purely in registers.
    float2 rvA[Dn], rvB[Dn];
    if (colth) {
        #pragma unroll
        for (int d = 0; d < Dn; ++d)
            rvA[d] = __ldcs(reinterpret_cast<const float2*>(gbase + d * D_STRIDE));
        const float* nb = gbase + cap_step;
        #pragma unroll
        for (int d = 0; d < Dn; ++d)
            rvB[d] = __ldcs(reinterpret_cast<const float2*>(nb + d * D_STRIDE));
    }

    auto process_cap = [&](float2 (&rv)[Dn], const int ic) {
        const int i = g * CAPS_PER_GROUP + ic;

        // register-only: norms for this thread's two columns, premultiply
        float n0 = 0.f, n1 = 0.f;
        if (colth) {
            #pragma unroll
            for (int d = 0; d < Dn; ++d) {
                n0 += rv[d].x * rv[d].x;
                n1 += rv[d].y * rv[d].y;
            }
            n0 = sqrtf(n0);
            n1 = sqrtf(n1);
            #pragma unroll
            for (int d = 0; d < Dn; ++d) {
                rv[d].x *= n0;
                rv[d].y *= n1;
            }
        }

        group_bar(barid);   // prev x1 compute done -> nx/nsm free
        if (colth) {
            #pragma unroll
            for (int d = 0; d < Dn; ++d)
                *reinterpret_cast<float2*>(&nxg[d * WK + 2 * lt]) = rv[d];
            *reinterpret_cast<float2*>(&nsg[2 * lt]) = make_float2(n0, n1);
            npg[lt] = n0 + n1;   // pair sum for fast den windows

            // prefetch cap ic+2 into the SAME buffer (consumed 2 iters later)
            if (ic + 2 < CAPS_PER_GROUP) {
                const float* nb = gbase + (size_t)(ic + 2) * cap_step;
                #pragma unroll
                for (int d = 0; d < Dn; ++d)
                    rv[d] = __ldcs(reinterpret_cast<const float2*>(nb + d * D_STRIDE));
            }
        }
        group_bar(barid);   // nx/nsm/nps populated

        // x1[i][d][w] = sum_k nx[d][w*9+k] / sum_k n[w*9+k]  (112 roles)
        // den via 4 pair sums + 1 edge scalar (window [9w,9w+8] pair-aligned
        // on one side for every w parity).
        float* const x1row = &x1s[i * DW];
        #pragma unroll
        for (int r = 0; r < 2; ++r) {
            const int t = lt + r * GSZ;
            if (t < DW) {
                const int d = t / Wn;
                const int w = t - d * Wn;
                const int jb = w * Kn;
                const int s = w & 1;
                const int pbase = (jb + s) >> 1;
                float den = nsg[jb + (s ? 0 : 8)];
                #pragma unroll
                for (int q = 0; q < 4; ++q) den += npg[pbase + q];
                float num = 0.f;
                #pragma unroll
                for (int k = 0; k < Kn; ++k) num += nxg[d * WK + jb + k];
                x1row[t] = num / den;
            }
        }
    };

    #pragma unroll
    for (int ic2 = 0; ic2 < CAPS_PER_GROUP; ic2 += 2) {
        process_cap(rvA, ic2);
        process_cap(rvB, ic2 + 1);
    }
    __syncthreads();        // all groups' x1 complete; stage-1 scratch dead

    // ---- n1[i][w] = ||x1_i|| ----
    for (int it = tid; it < In * Wn; it += NT) {
        const int i = it / Wn, w = it - i * Wn;
        const float* p = &x1s[i * DW + w];
        float s = 0.f;
        #pragma unroll
        for (int d = 0; d < Dn; ++d) {
            const float v = p[d * Wn];
            s += v * v;
        }
        u.s2.n1s[it] = sqrtf(s);
    }
    __syncthreads();

    // ---- consensus v[d][w] ----
    if (tid < DW) {
        float num = 0.f, den = 0.f;
        const float* p = &x1s[tid];
        const float* q = &u.s2.n1s[ww];
        #pragma unroll
        for (int i = 0; i < In; ++i) {
            const float n = q[i * Wn];
            num += n * p[i * DW];
            den += n;
        }
        u.s2.vsh[tid] = num / den;
    }
    __syncthreads();

    // ---- losses[i][w] = -v . x1_i  (written transposed) ----
    for (int it = tid; it < In * Wn; it += NT) {
        const int i = it / Wn, w = it - i * Wn;
        const float* p = &x1s[i * DW + w];
        float s = 0.f;
        #pragma unroll
        for (int d = 0; d < Dn; ++d)
            s += u.s2.vsh[d * Wn + w] * p[d * Wn];
        u.s2.lossT[w * LT_PITCH + i] = -s;
    }
    __syncthreads();

    // ---- threshold via warp max-elimination + fused selection ----
    // thr(w) = 7th largest of 32 losses = sorted_asc[SUBSET-1]. One warp per
    // site: lanes hold l_i; 7 rounds of (warp-max, remove one argmax lane).
    {
        #pragma unroll
        for (int rep = 0; rep < 2; ++rep) {
            const int w = wid + rep * 8;
            if (w < Wn) {
                const float l = u.s2.lossT[w * LT_PITCH + lane];
                bool alive = true;
                float thr = 0.f;
                #pragma unroll
                for (int r = 0; r < NDROP; ++r) {
                    float v = alive ? l : -FLT_MAX;
                    #pragma unroll
                    for (int off = 16; off; off >>= 1)
                        v = fmaxf(v, __shfl_xor_sync(FULLM, v, off));
                    thr = v;
                    if (r < NDROP - 1) {
                        const unsigned bal =
                            __ballot_sync(FULLM, alive && (l == v));
                        if (lane == __ffs(bal) - 1) alive = false;
                    }
                }
                const float n1v = u.s2.n1s[lane * Wn + w];
                const float wsel = (l <= thr) ? n1v : 0.f;
                u.s2.wselT[w * LT_PITCH + lane] = wsel;
                float dsum = wsel;
                #pragma unroll
                for (int off = 16; off; off >>= 1)
                    dsum += __shfl_xor_sync(FULLM, dsum, off);
                if (lane == 0) u.s2.denf[w] = dsum;
            }
        }
    }
    __syncthreads();

    // ---- final weighted average over chosen subset ----
    if (tid < DW) {
        float num = 0.f;
        const float* p = &x1s[tid];
        const float* ws = &u.s2.wselT[ww * LT_PITCH];
        #pragma unroll
        for (int i = 0; i < In; ++i)
            num += ws[i] * p[i * DW];
        out[((size_t)((b * On + o) * Dn + dd) * Hn + h) * Wn + ww] =
            num / u.s2.denf[ww];
    }
}

extern "C" void kernel_launch(void* const* d_in, const int* in_sizes, int n_in,
                              void* d_out, int out_size) {
    const float* x = (const float*)d_in[0];
    float* out = (float*)d_out;
    conv_subset_routing_kernel<<<Bn * On * Hn, NT>>>(x, out);
}

// round 14
// speedup vs baseline: 1.1477x; 1.1477x over previous
#include <cuda_runtime.h>
#include <float.h>
#include <math.h>

// Problem constants
#define Bn 8
#define In 32
#define On 32
#define Dn 8
#define Hn 14
#define Wn 14
#define Kn 9
#define WK 126
#define NT 256
#define CAPS_PER_GROUP 8         // 4 groups x 8 caps = 32
#define SUBSET 26                // ceil(0.8 * 32)
#define NDROP (In - SUBSET + 1)  // 7: threshold = 7th largest
#define D_STRIDE (Hn*WK)         // 1764 floats between d-planes
#define CAP_STRIDE (Dn*D_STRIDE) // 14112 floats between capsules
#define DW (Dn*Wn)               // 112
#define LT_PITCH 33
#define FULLM 0xFFFFFFFFu

__global__ __launch_bounds__(NT, 5)
void conv_subset_routing_kernel(const float* __restrict__ x,
                                float* __restrict__ out) {
    // transposed x1: x1t[i*112 + w*8 + d]  (d contiguous -> float4 everywhere)
    __shared__ __align__(16) float x1t[In * DW];
    __shared__ float n1s[In * Wn];          // n1s[i*14 + w]
    __shared__ float lossT[Wn * LT_PITCH];  // lossT[w*33 + i]
    __shared__ float wselT[Wn * LT_PITCH];
    __shared__ __align__(16) float vsh[DW]; // vsh[w*8 + d]
    __shared__ float denf[Wn];

    const int tid = threadIdx.x;
    const int bid = blockIdx.x;
    const int h = bid % Hn;
    const int o = (bid / Hn) % On;
    const int b = bid / (Hn * On);

    const int g    = tid >> 6;        // group 0..3 (8 caps each)
    const int wg   = (tid >> 5) & 1;  // warp within group
    const int lane = tid & 31;
    const int wid  = tid >> 5;

    const size_t bo_base = (size_t)(b * In * On + o) * CAP_STRIDE + (size_t)h * WK;
    const size_t cap_step = (size_t)On * CAP_STRIDE;

    // warp0 owns cols 0..63 (windows 0-6); warp1 owns cols 62..125 (windows
    // 7-13). 2-col overlap => warps fully independent: NO stage-1 barriers.
    const int colb = wg ? (62 + 2 * lane) : (2 * lane);
    const float* gptr = x + bo_base + (size_t)(g * CAPS_PER_GROUP) * cap_step + colb;

    // owner-lane window assignment: owner = lane holding the window's edge col.
    // even-start window: sum = shfl_up(s4,4) + a0 ; odd-start: sum = a1 + shfl_down(s4,1)
    int wE = -1, wO = -1;
    if (wg == 0) {
        if (lane % 9 == 4) { const int k = lane / 9; wE = 2 * k; wO = (lane == 31) ? -1 : 2 * k + 1; }
    } else {
        if (lane % 9 == 0) { const int k = lane / 9; wO = 7 + 2 * k; wE = k ? (6 + 2 * k) : -1; }
    }

    // ---- stage 1: per-cap weighted average over kernel positions ----
    for (int ic = 0; ic < CAPS_PER_GROUP; ++ic) {
        const int i = g * CAPS_PER_GROUP + ic;
        const float* p = gptr + (size_t)ic * cap_step;

        float2 rv[Dn];
        #pragma unroll
        for (int d = 0; d < Dn; ++d)
            rv[d] = __ldcs(reinterpret_cast<const float2*>(p + d * D_STRIDE));

        // per-column norms over D (register-only)
        float n0 = 0.f, n1 = 0.f;
        #pragma unroll
        for (int d = 0; d < Dn; ++d) {
            n0 += rv[d].x * rv[d].x;
            n1 += rv[d].y * rv[d].y;
        }
        n0 = sqrtf(n0);
        n1 = sqrtf(n1);
        #pragma unroll
        for (int d = 0; d < Dn; ++d) {
            rv[d].x *= n0;
            rv[d].y *= n1;
        }

        // den windows via shuffle tree on n
        {
            const float pq = n0 + n1;
            const float s2 = pq + __shfl_down_sync(FULLM, pq, 1);
            const float s4 = s2 + __shfl_down_sync(FULLM, s2, 2);
            const float dU = __shfl_up_sync(FULLM, s4, 4);
            const float dD = __shfl_down_sync(FULLM, s4, 1);
            const float denE = dU + n0;
            const float denO = n1 + dD;
            const float invE = (wE >= 0) ? (1.0f / denE) : 0.f;
            const float invO = (wO >= 0) ? (1.0f / denO) : 0.f;

            // num windows per d via same shuffle tree; owners scale by invden
            float xe[Dn], xo[Dn];
            #pragma unroll
            for (int d = 0; d < Dn; ++d) {
                const float pd = rv[d].x + rv[d].y;
                const float t2 = pd + __shfl_down_sync(FULLM, pd, 1);
                const float t4 = t2 + __shfl_down_sync(FULLM, t2, 2);
                const float fU = __shfl_up_sync(FULLM, t4, 4);
                const float fD = __shfl_down_sync(FULLM, t4, 1);
                xe[d] = (fU + rv[d].x) * invE;
                xo[d] = (rv[d].y + fD) * invO;
            }

            float* row = &x1t[i * DW];
            if (wE >= 0) {
                *reinterpret_cast<float4*>(&row[wE * 8])     = make_float4(xe[0], xe[1], xe[2], xe[3]);
                *reinterpret_cast<float4*>(&row[wE * 8 + 4]) = make_float4(xe[4], xe[5], xe[6], xe[7]);
            }
            if (wO >= 0) {
                *reinterpret_cast<float4*>(&row[wO * 8])     = make_float4(xo[0], xo[1], xo[2], xo[3]);
                *reinterpret_cast<float4*>(&row[wO * 8 + 4]) = make_float4(xo[4], xo[5], xo[6], xo[7]);
            }
        }
    }
    __syncthreads();        // first and only stage-1 -> stage-2 barrier

    // ---- n1[i][w] = ||x1_i|| ----
    for (int it = tid; it < In * Wn; it += NT) {
        const int i = it / Wn, w = it - i * Wn;
        const float4 a = *reinterpret_cast<const float4*>(&x1t[i * DW + w * 8]);
        const float4 c = *reinterpret_cast<const float4*>(&x1t[i * DW + w * 8 + 4]);
        const float s = a.x*a.x + a.y*a.y + a.z*a.z + a.w*a.w
                      + c.x*c.x + c.y*c.y + c.z*c.z + c.w*c.w;
        n1s[it] = sqrtf(s);
    }
    __syncthreads();

    // ---- consensus v[w*8+d] ----
    if (tid < DW) {
        const int w = tid >> 3;
        float num = 0.f, den = 0.f;
        #pragma unroll
        for (int i = 0; i < In; ++i) {
            const float n = n1s[i * Wn + w];
            num += n * x1t[i * DW + tid];
            den += n;
        }
        vsh[tid] = num / den;
    }
    __syncthreads();

    // ---- losses[i][w] = -v . x1_i  (transposed store) ----
    for (int it = tid; it < In * Wn; it += NT) {
        const int i = it / Wn, w = it - i * Wn;
        const float4 a = *reinterpret_cast<const float4*>(&x1t[i * DW + w * 8]);
        const float4 c = *reinterpret_cast<const float4*>(&x1t[i * DW + w * 8 + 4]);
        const float4 va = *reinterpret_cast<const float4*>(&vsh[w * 8]);
        const float4 vc = *reinterpret_cast<const float4*>(&vsh[w * 8 + 4]);
        const float s = va.x*a.x + va.y*a.y + va.z*a.z + va.w*a.w
                      + vc.x*c.x + vc.y*c.y + vc.z*c.z + vc.w*c.w;
        lossT[w * LT_PITCH + i] = -s;
    }
    __syncthreads();

    // ---- threshold via warp max-elimination + fused selection ----
    // thr(w) = 7th largest of 32 losses = sorted_asc[SUBSET-1].
    {
        #pragma unroll
        for (int rep = 0; rep < 2; ++rep) {
            const int w = wid + rep * 8;
            if (w < Wn) {
                const float l = lossT[w * LT_PITCH + lane];
                bool alive = true;
                float thr = 0.f;
                #pragma unroll
                for (int r = 0; r < NDROP; ++r) {
                    float v = alive ? l : -FLT_MAX;
                    #pragma unroll
                    for (int off = 16; off; off >>= 1)
                        v = fmaxf(v, __shfl_xor_sync(FULLM, v, off));
                    thr = v;
                    if (r < NDROP - 1) {
                        const unsigned bal = __ballot_sync(FULLM, alive && (l == v));
                        if (lane == __ffs(bal) - 1) alive = false;
                    }
                }
                const float n1v = n1s[lane * Wn + w];
                const float wsel = (l <= thr) ? n1v : 0.f;
                wselT[w * LT_PITCH + lane] = wsel;
                float dsum = wsel;
                #pragma unroll
                for (int off = 16; off; off >>= 1)
                    dsum += __shfl_xor_sync(FULLM, dsum, off);
                if (lane == 0) denf[w] = dsum;
            }
        }
    }
    __syncthreads();

    // ---- final weighted average over chosen subset ----
    if (tid < DW) {
        const int w = tid >> 3;
        const int d = tid & 7;
        float num = 0.f;
        const float* ws = &wselT[w * LT_PITCH];
        #pragma unroll
        for (int i = 0; i < In; ++i)
            num += ws[i] * x1t[i * DW + tid];
        out[((size_t)((b * On + o) * Dn + d) * Hn + h) * Wn + w] = num / denf[w];
    }
}

extern "C" void kernel_launch(void* const* d_in, const int* in_sizes, int n_in,
                              void* d_out, int out_size) {
    const float* x = (const float*)d_in[0];
    float* out = (float*)d_out;
    conv_subset_routing_kernel<<<Bn * On * Hn, NT>>>(x, out);
}